// round 16
// baseline (speedup 1.0000x reference)
#include <cuda_runtime.h>
#include <cuda_fp16.h>
#include <cstdint>
#include <cstring>

#define BB   2
#define NC   6
#define CCH  256
#define FHH  28
#define FWW  50
#define HWF  (FHH*FWW)      // 1400
#define HWP  1408           // padded M for HMMA (22 * 64)
#define PP   40000
#define ZZ   3
#define NR   (ZZ*NC)        // 18 record slots per (b,p)

// u_norm = u * (fW/IMG_W) / (fW-1) * 2 - 1
__device__ __constant__ float CU2 = (float)((50.0/1600.0)/49.0*2.0);
__device__ __constant__ float CV2 = (float)((28.0/900.0)/27.0*2.0);

// Scratch (zero-initialized device globals; no allocations anywhere)
__device__ __half  g_featC[(size_t)BB*NC*HWF*CCH + 64*CCH]; // fp16 conv-ed features + OOB pad (stays 0)
__device__ __half  g_featH[(size_t)BB*NC*HWP*CCH];          // fp16 feats transposed [bn][hw][c], rows>=1400 zero
__device__ __half  g_whT[CCH*CCH];                          // fp16 W transposed: whT[c][o]
__device__ int     g_cnt[BB*PP];                            // valid-record count per (b,p)
__device__ int     g_crec[BB*PP*NR + 32];                   // compacted records: full feature offset (pad stays 0)
__device__ float4  g_cw[BB*PP*NR + 32];                     // compacted weights (pre-scaled by invc/3; pad stays 0)
__device__ float   g_cam[BB*NC*12];                         // fused K*E_inv per camera: M[9], c[3]

// ---------------------------------------------------------------------------
// Kernel 1a: W (o,c) fp32 -> whT (c,o) fp16
// ---------------------------------------------------------------------------
__global__ void prep_w(const float* __restrict__ w)
{
    int t = blockIdx.x * 256 + threadIdx.x;   // 65536 threads
    int c = t >> 8, o = t & 255;
    g_whT[c*CCH + o] = __float2half(w[o*CCH + c]);
}

// ---------------------------------------------------------------------------
// Kernel 1b: feats [bn][c][hw] fp32 -> g_featH [bn][hw][c] fp16 (32x32 tiles)
// ---------------------------------------------------------------------------
__global__ void prep_feats(const float* __restrict__ feats)
{
    __shared__ float t[32][33];
    const int bn  = blockIdx.z;
    const int hw0 = blockIdx.x * 32;
    const int c0  = blockIdx.y * 32;
    const int tx  = threadIdx.x, ty = threadIdx.y;   // 32 x 8

    const float* src = feats + (size_t)bn * CCH * HWF;
#pragma unroll
    for (int r = 0; r < 4; r++) {
        int c  = c0 + ty + r * 8;
        int hw = hw0 + tx;
        t[ty + r*8][tx] = (hw < HWF) ? src[(size_t)c * HWF + hw] : 0.f;
    }
    __syncthreads();
    __half* dst = g_featH + (size_t)bn * HWP * CCH;
#pragma unroll
    for (int r = 0; r < 4; r++) {
        int i  = ty + r * 8;                 // local hw
        int hw = hw0 + i;                    // < 1408 always
        dst[(size_t)hw * CCH + c0 + tx] = __float2half(t[tx][i]);
    }
}

// ---------------------------------------------------------------------------
// Kernel 1c: fuse K * E_inv per camera. M = K * R^T, c = K * (-R^T t).
// ---------------------------------------------------------------------------
__global__ void prep_cam(const float* __restrict__ intr,
                         const float* __restrict__ extr)
{
    int bn = threadIdx.x;
    if (bn >= BB * NC) return;
    const float* E = extr + bn * 16;
    const float* K = intr + bn * 9;

    float Rt[9];
#pragma unroll
    for (int i = 0; i < 3; i++)
#pragma unroll
        for (int j = 0; j < 3; j++)
            Rt[i*3 + j] = E[j*4 + i];
    float t0 = E[3], t1 = E[7], t2 = E[11];
    float tp[3];
#pragma unroll
    for (int i = 0; i < 3; i++)
        tp[i] = -(Rt[i*3+0]*t0 + Rt[i*3+1]*t1 + Rt[i*3+2]*t2);

    float* o = g_cam + bn * 12;
#pragma unroll
    for (int i = 0; i < 3; i++) {
#pragma unroll
        for (int j = 0; j < 3; j++)
            o[i*3 + j] = K[i*3+0]*Rt[0*3+j] + K[i*3+1]*Rt[1*3+j] + K[i*3+2]*Rt[2*3+j];
        o[9 + i] = K[i*3+0]*tp[0] + K[i*3+1]*tp[1] + K[i*3+2]*tp[2];
    }
}

// ---------------------------------------------------------------------------
// Kernel 2: HMMA GEMM per (b,n): featC[hw][o] = sum_c featH[hw][c] * W[o][c]
// BM=64, BN=256, BK=32; 8 warps = 2m x 4n, warp tile m32 n64. cp.async
// double-buffered tile prefetch + smem-staged coalesced epilogue.
// (unchanged from R15, best measured conv variant)
// ---------------------------------------------------------------------------
#define GBM 64
#define GBK 32
#define ASTR 40       // 32 + 8 pad halves
#define BSTR 264      // 256 + 8 pad halves
#define ESTR 264      // epilogue staging stride
#define SMEM_BYTES (2*GBM*ASTR*2 + 2*GBK*BSTR*2)   // 44032

__device__ __forceinline__ uint32_t smem_u32(const void* p)
{
    return (uint32_t)__cvta_generic_to_shared(p);
}

__device__ __forceinline__ void cp_async16(uint32_t saddr, const void* gaddr)
{
    asm volatile("cp.async.cg.shared.global [%0], [%1], 16;" :: "r"(saddr), "l"(gaddr));
}
__device__ __forceinline__ void cp_commit()  { asm volatile("cp.async.commit_group;"); }
__device__ __forceinline__ void cp_wait0()   { asm volatile("cp.async.wait_group 0;"); }

__device__ __forceinline__ void ldm_x4(uint32_t* r, uint32_t addr)
{
    asm volatile("ldmatrix.sync.aligned.m8n8.x4.shared.b16 {%0,%1,%2,%3}, [%4];"
                 : "=r"(r[0]), "=r"(r[1]), "=r"(r[2]), "=r"(r[3]) : "r"(addr));
}
__device__ __forceinline__ void ldm_x4t(uint32_t* r, uint32_t addr)
{
    asm volatile("ldmatrix.sync.aligned.m8n8.x4.trans.shared.b16 {%0,%1,%2,%3}, [%4];"
                 : "=r"(r[0]), "=r"(r[1]), "=r"(r[2]), "=r"(r[3]) : "r"(addr));
}
__device__ __forceinline__ void mma16816(float* d, const uint32_t* a, const uint32_t* b)
{
    asm volatile("mma.sync.aligned.m16n8k16.row.col.f32.f16.f16.f32 "
                 "{%0,%1,%2,%3}, {%4,%5,%6,%7}, {%8,%9}, {%0,%1,%2,%3};"
                 : "+f"(d[0]), "+f"(d[1]), "+f"(d[2]), "+f"(d[3])
                 : "r"(a[0]), "r"(a[1]), "r"(a[2]), "r"(a[3]), "r"(b[0]), "r"(b[1]));
}

__global__ __launch_bounds__(256, 2) void conv_hmma()
{
    const int bn = blockIdx.y;              // 0..11
    const int m0 = blockIdx.x * GBM;

    __shared__ __align__(16) char smem_raw[SMEM_BYTES];
    __half (*As)[GBM * ASTR] = (__half(*)[GBM * ASTR])smem_raw;
    __half (*Bs)[GBK * BSTR] = (__half(*)[GBK * BSTR])(smem_raw + 2 * GBM * ASTR * 2);

    const int tid  = threadIdx.x;
    const int lane = tid & 31;
    const int wid  = tid >> 5;
    const int wm   = wid >> 2;              // 0..1
    const int wn   = wid & 3;               // 0..3

    const __half* A = g_featH + (size_t)bn * HWP * CCH;

    float acc[2][8][4];
#pragma unroll
    for (int i = 0; i < 2; i++)
#pragma unroll
        for (int j = 0; j < 8; j++)
#pragma unroll
            for (int q = 0; q < 4; q++) acc[i][j][q] = 0.f;

    const int ar = tid >> 2;                // A row 0..63
    const int ah = (tid & 3) * 8;           // A half-offset within 32

    cp_async16(smem_u32(&As[0][ar * ASTR + ah]),
               &A[(size_t)(m0 + ar) * CCH + ah]);
#pragma unroll
    for (int s = 0; s < 4; s++) {
        int v = tid + 256 * s;              // 0..1023
        int row = v >> 5, c = (v & 31) * 8;
        cp_async16(smem_u32(&Bs[0][row * BSTR + c]),
                   &g_whT[(size_t)row * CCH + c]);
    }
    cp_commit();
    cp_wait0();
    __syncthreads();

    int buf = 0;
#pragma unroll 1
    for (int kt = 0; kt < CCH / GBK; kt++) {
        const bool more = (kt + 1 < CCH / GBK);
        if (more) {
            int k0 = (kt + 1) * GBK;
            cp_async16(smem_u32(&As[buf ^ 1][ar * ASTR + ah]),
                       &A[(size_t)(m0 + ar) * CCH + k0 + ah]);
#pragma unroll
            for (int s = 0; s < 4; s++) {
                int v = tid + 256 * s;
                int row = v >> 5, c = (v & 31) * 8;
                cp_async16(smem_u32(&Bs[buf ^ 1][row * BSTR + c]),
                           &g_whT[(size_t)(k0 + row) * CCH + c]);
            }
            cp_commit();
        }

#pragma unroll
        for (int h = 0; h < 2; h++) {
            const int kk = h * 16;
            uint32_t af[2][4];
#pragma unroll
            for (int i = 0; i < 2; i++) {
                uint32_t addr = smem_u32(&As[buf][(wm*32 + i*16 + (lane & 15)) * ASTR
                                                  + (lane >> 4) * 8 + kk]);
                ldm_x4(af[i], addr);
            }
            uint32_t bf[8][2];
#pragma unroll
            for (int j4 = 0; j4 < 4; j4++) {
                uint32_t r[4];
                uint32_t addr = smem_u32(&Bs[buf][(kk + ((lane >> 3) & 1) * 8 + (lane & 7)) * BSTR
                                                  + wn*64 + j4*16 + (lane >> 4) * 8]);
                ldm_x4t(r, addr);
                bf[2*j4][0]   = r[0]; bf[2*j4][1]   = r[1];
                bf[2*j4+1][0] = r[2]; bf[2*j4+1][1] = r[3];
            }
#pragma unroll
            for (int i = 0; i < 2; i++)
#pragma unroll
                for (int j = 0; j < 8; j++)
                    mma16816(acc[i][j], af[i], bf[j]);
        }

        if (more) cp_wait0();
        __syncthreads();
        buf ^= 1;
    }

    // ---- Epilogue: stage fp16 tile in smem, then coalesced row stores ----
    __half* stg = (__half*)smem_raw;        // 64 x ESTR halves = 33792 B
    const int gid = lane >> 2;              // 0..7
    const int tig = lane & 3;               // 0..3
#pragma unroll
    for (int i = 0; i < 2; i++) {
        int r0 = wm*32 + i*16 + gid;
#pragma unroll
        for (int j = 0; j < 8; j++) {
            int c0 = wn*64 + j*8 + tig*2;
            *(__half2*)&stg[r0 * ESTR + c0]       = __floats2half2_rn(acc[i][j][0], acc[i][j][1]);
            *(__half2*)&stg[(r0 + 8) * ESTR + c0] = __floats2half2_rn(acc[i][j][2], acc[i][j][3]);
        }
    }
    __syncthreads();

    __half* D = g_featC + (size_t)bn * HWF * CCH;
#pragma unroll
    for (int pass = 0; pass < 8; pass++) {
        int row  = pass * 8 + wid;          // 0..63, one row per warp per pass
        int grow = m0 + row;
        if (grow < HWF) {
            uint4 v = *(const uint4*)&stg[row * ESTR + lane * 8];
            *(uint4*)&D[(size_t)grow * CCH + lane * 8] = v;
        }
    }
}

// ---------------------------------------------------------------------------
// Kernel 3: projection + record compaction (unchanged)
// ---------------------------------------------------------------------------
__global__ __launch_bounds__(256) void proj_kernel(const float* __restrict__ pts)
{
    int t = blockIdx.x * blockDim.x + threadIdx.x;
    if (t >= BB * PP) return;
    int p = t % PP;
    int b = t / PP;

    const int base = (b * PP + p) * NR;
    int s = 0;

#pragma unroll
    for (int z = 0; z < ZZ; z++) {
        const float* q = pts + ((size_t)z * PP + p) * 3;
        float px = q[0], py = q[1], pz = q[2];
        float cnt = 0.f;

        int    ibuf[NC];
        float4 wbuf[NC];

#pragma unroll
        for (int n = 0; n < NC; n++) {
            const float* Cm = g_cam + (b * NC + n) * 12;
            float Zc = Cm[6]*px + Cm[7]*py + Cm[8]*pz + Cm[11];
            float inv = 1.f / (Zc + 1e-6f);
            float un = (Cm[0]*px + Cm[1]*py + Cm[2]*pz + Cm[9])  * inv * CU2 - 1.f;
            float vn = (Cm[3]*px + Cm[4]*py + Cm[5]*pz + Cm[10]) * inv * CV2 - 1.f;
            bool valid = (Zc > 0.1f) && (un >= -1.f) && (un <= 1.f) && (vn >= -1.f) && (vn <= 1.f);

            int off = -1;
            float4 w = make_float4(0.f, 0.f, 0.f, 0.f);
            if (valid) {
                float x = (un + 1.f) * 0.5f * (float)(FWW - 1);
                float y = (vn + 1.f) * 0.5f * (float)(FHH - 1);
                float x0f = floorf(x), y0f = floorf(y);
                float wx1 = x - x0f, wy1 = y - y0f;
                float wx0 = 1.f - wx1, wy0 = 1.f - wy1;
                int x0 = (int)x0f, y0 = (int)y0f;
                w = make_float4(wx0 * wy0, wx1 * wy0, wx0 * wy1, wx1 * wy1);
                if (x0 >= FWW - 1) { w.y = 0.f; w.w = 0.f; }  // x1 OOB -> weight 0
                if (y0 >= FHH - 1) { w.z = 0.f; w.w = 0.f; }
                off = (b * NC + n) * HWF + y0 * FWW + x0;
                cnt += 1.f;
            }
            ibuf[n] = off;
            wbuf[n] = w;
        }

        float icc = (1.f / (cnt + 1e-6f)) * (1.f / 3.f);
#pragma unroll
        for (int n = 0; n < NC; n++) {
            if (ibuf[n] >= 0) {
                float4 w = wbuf[n];
                w.x *= icc; w.y *= icc; w.z *= icc; w.w *= icc;
                g_crec[base + s] = ibuf[n];
                g_cw[base + s]   = w;
                s++;
            }
        }
    }
    g_cnt[b * PP + p] = s;
}

// ---------------------------------------------------------------------------
// Kernel 4: fp16 sampling. NEW: ping-pong (A/B) corner-register sets with
// unroll-by-2 record processing — eliminates the per-record pipeline-shift
// MOVs (~21/record -> ~9 per 2 records). cnt rounded up to even; padded
// slots are zero (offset 0, weight 0) so the extra half-iteration adds 0
// via an L1-hot benign load. Packed f32x2 accumulation, smem BN table,
// coalesced transposed output (all as in the 118.6us configuration).
// ---------------------------------------------------------------------------
__device__ __forceinline__ unsigned long long pack2f(float w)
{
    unsigned long long r;
    uint32_t u = __float_as_uint(w);
    asm("mov.b64 %0, {%1, %1};" : "=l"(r) : "r"(u));
    return r;
}

// acc: 4 packed float2 accumulators; q: 8 halves; w2: packed (w,w)
__device__ __forceinline__ void accum8x2(unsigned long long* acc, const uint4& q,
                                         unsigned long long w2)
{
    const __half2* h = (const __half2*)&q;
#pragma unroll
    for (int j = 0; j < 4; j++) {
        float2 f = __half22float2(h[j]);
        unsigned long long fu;
        memcpy(&fu, &f, 8);
        asm("fma.rn.f32x2 %0, %1, %2, %0;" : "+l"(acc[j]) : "l"(fu), "l"(w2));
    }
}

__global__ __launch_bounds__(256, 3) void sample_kernel(const float* __restrict__ convb,
                                                        const float* __restrict__ gamma,
                                                        const float* __restrict__ beta,
                                                        const float* __restrict__ mean,
                                                        const float* __restrict__ var,
                                                        float* __restrict__ out)
{
    __shared__ float so[16 * 257];
    __shared__ float ssc[CCH], sbi[CCH];

    const int b   = blockIdx.y;
    const int p0  = blockIdx.x * 32;
    const int tid = threadIdx.x;
    const int cg  = tid & 31;     // channel group (8 channels)
    const int ps  = tid >> 5;     // warp id = pixel sub-lane 0..7
    const int o0  = cg * 8;

    // BN + conv bias epilogue constants -> smem (one channel per thread)
    {
        float s = gamma[tid] * rsqrtf(var[tid] + 1e-5f);
        ssc[tid] = s;
        sbi[tid] = (convb[tid] - mean[tid]) * s + beta[tid];
    }
    __syncthreads();

    const uint4* fc = (const uint4*)g_featC;
    const size_t ob = (size_t)b * CCH * PP + p0;

#pragma unroll 1
    for (int chunk = 0; chunk < 2; chunk++) {
#pragma unroll 1
        for (int i = 0; i < 2; i++) {
            const int lp = i * 8 + ps;            // local pixel 0..15
            const int p  = p0 + chunk * 16 + lp;

            const int pb   = b * PP + p;
            const int cnt2 = (g_cnt[pb] + 1) & ~1;  // round up to even
            const int base = pb * NR;

            unsigned long long acc[4] = {0ull, 0ull, 0ull, 0ull};

            // prologue: meta for records 0,1; corner data for record 0 (A set)
            float4 wA   = g_cw[base];
            int    offB = g_crec[base + 1];
            float4 wB   = g_cw[base + 1];
            const uint4* fA = fc + (size_t)g_crec[base] * 32 + cg;
            uint4 a0 = fA[0], a1 = fA[32], a2 = fA[FWW * 32], a3 = fA[(FWW + 1) * 32];

#pragma unroll 1
            for (int s = 0; s < cnt2; s += 2) {
                // issue B corner loads (record s+1)
                const uint4* fB = fc + (size_t)offB * 32 + cg;
                uint4 b0 = fB[0], b1 = fB[32], b2 = fB[FWW * 32], b3 = fB[(FWW + 1) * 32];
                // meta for records s+2, s+3 (padded arrays: safe over-read)
                int    offA2 = g_crec[base + s + 2];
                float4 wA2   = g_cw[base + s + 2];
                int    offB2 = g_crec[base + s + 3];
                float4 wB2   = g_cw[base + s + 3];
                // accumulate A (record s; its loads issued last iteration)
                accum8x2(acc, a0, pack2f(wA.x));
                accum8x2(acc, a1, pack2f(wA.y));
                accum8x2(acc, a2, pack2f(wA.z));
                accum8x2(acc, a3, pack2f(wA.w));
                // issue A corner loads for record s+2
                const uint4* fA2 = fc + (size_t)offA2 * 32 + cg;
                a0 = fA2[0]; a1 = fA2[32]; a2 = fA2[FWW * 32]; a3 = fA2[(FWW + 1) * 32];
                // accumulate B (record s+1)
                accum8x2(acc, b0, pack2f(wB.x));
                accum8x2(acc, b1, pack2f(wB.y));
                accum8x2(acc, b2, pack2f(wB.z));
                accum8x2(acc, b3, pack2f(wB.w));
                // loop-carried meta
                wA = wA2; wB = wB2; offB = offB2;
            }

            float ao[8];
            memcpy(ao, acc, 32);
            int row = lp * 257 + o0;
#pragma unroll
            for (int j = 0; j < 8; j++)
                so[row + j] = fmaxf(fmaf(ao[j], ssc[o0 + j], sbi[o0 + j]), 0.f);
        }
        __syncthreads();

        // Transposed write-out: 16 consecutive threads write 16 consecutive
        // pixels of one o-row (64B coalesced stores).
        const int px = tid & 15;
        const int og = tid >> 4;          // 0..15
#pragma unroll
        for (int ot = 0; ot < 16; ot++) {
            int o = og + ot * 16;
            out[ob + (size_t)o * PP + chunk * 16 + px] = so[px * 257 + o];
        }
        __syncthreads();
    }
}

// ---------------------------------------------------------------------------
extern "C" void kernel_launch(void* const* d_in, const int* in_sizes, int n_in,
                              void* d_out, int out_size)
{
    const float* feats = (const float*)d_in[0];
    const float* intr  = (const float*)d_in[1];
    const float* extr  = (const float*)d_in[2];
    const float* pts   = (const float*)d_in[3];
    const float* convw = (const float*)d_in[4];
    const float* convb = (const float*)d_in[5];
    const float* gamma = (const float*)d_in[6];
    const float* beta  = (const float*)d_in[7];
    const float* mean  = (const float*)d_in[8];
    const float* var   = (const float*)d_in[9];
    float* out = (float*)d_out;

    prep_w<<<256, 256>>>(convw);
    prep_feats<<<dim3(HWP/32, CCH/32, BB*NC), dim3(32, 8)>>>(feats);
    prep_cam<<<1, 32>>>(intr, extr);
    conv_hmma<<<dim3(HWP/GBM, BB*NC), 256>>>();
    proj_kernel<<<(BB * PP + 255) / 256, 256>>>(pts);
    sample_kernel<<<dim3(PP / 32, BB), 256>>>(convb, gamma, beta, mean, var, out);
}

// round 17
// speedup vs baseline: 1.0687x; 1.0687x over previous
#include <cuda_runtime.h>
#include <cuda_fp16.h>
#include <cstdint>
#include <cstring>

#define BB   2
#define NC   6
#define CCH  256
#define FHH  28
#define FWW  50
#define HWF  (FHH*FWW)      // 1400
#define HWP  1408           // padded M for HMMA (22 * 64)
#define PP   40000
#define ZZ   3
#define NR   (ZZ*NC)        // 18 record slots per (b,p)

// u_norm = u * (fW/IMG_W) / (fW-1) * 2 - 1
__device__ __constant__ float CU2 = (float)((50.0/1600.0)/49.0*2.0);
__device__ __constant__ float CV2 = (float)((28.0/900.0)/27.0*2.0);

// Scratch (zero-initialized device globals; no allocations anywhere)
__device__ __half  g_featC[(size_t)BB*NC*HWF*CCH + 64*CCH]; // fp16 conv-ed features + OOB pad (stays 0)
__device__ __half  g_featH[(size_t)BB*NC*HWP*CCH];          // fp16 feats transposed [bn][hw][c], rows>=1400 zero
__device__ __half  g_whT[CCH*CCH];                          // fp16 W transposed: whT[c][o]
__device__ int     g_cnt[BB*PP];                            // valid-record count per (b,p)
__device__ int     g_crec[BB*PP*NR + 16];                   // compacted records: full feature offset (pad stays 0)
__device__ float4  g_cw[BB*PP*NR + 16];                     // compacted weights (pre-scaled by invc/3; pad stays 0)
__device__ float   g_cam[BB*NC*12];                         // fused K*E_inv per camera: M[9], c[3]

// ---------------------------------------------------------------------------
// Kernel 1a: W (o,c) fp32 -> whT (c,o) fp16
// ---------------------------------------------------------------------------
__global__ void prep_w(const float* __restrict__ w)
{
    int t = blockIdx.x * 256 + threadIdx.x;   // 65536 threads
    int c = t >> 8, o = t & 255;
    g_whT[c*CCH + o] = __float2half(w[o*CCH + c]);
}

// ---------------------------------------------------------------------------
// Kernel 1b: feats [bn][c][hw] fp32 -> g_featH [bn][hw][c] fp16 (32x32 tiles)
// ---------------------------------------------------------------------------
__global__ void prep_feats(const float* __restrict__ feats)
{
    __shared__ float t[32][33];
    const int bn  = blockIdx.z;
    const int hw0 = blockIdx.x * 32;
    const int c0  = blockIdx.y * 32;
    const int tx  = threadIdx.x, ty = threadIdx.y;   // 32 x 8

    const float* src = feats + (size_t)bn * CCH * HWF;
#pragma unroll
    for (int r = 0; r < 4; r++) {
        int c  = c0 + ty + r * 8;
        int hw = hw0 + tx;
        t[ty + r*8][tx] = (hw < HWF) ? src[(size_t)c * HWF + hw] : 0.f;
    }
    __syncthreads();
    __half* dst = g_featH + (size_t)bn * HWP * CCH;
#pragma unroll
    for (int r = 0; r < 4; r++) {
        int i  = ty + r * 8;                 // local hw
        int hw = hw0 + i;                    // < 1408 always
        dst[(size_t)hw * CCH + c0 + tx] = __float2half(t[tx][i]);
    }
}

// ---------------------------------------------------------------------------
// Kernel 1c: fuse K * E_inv per camera. M = K * R^T, c = K * (-R^T t).
// ---------------------------------------------------------------------------
__global__ void prep_cam(const float* __restrict__ intr,
                         const float* __restrict__ extr)
{
    int bn = threadIdx.x;
    if (bn >= BB * NC) return;
    const float* E = extr + bn * 16;
    const float* K = intr + bn * 9;

    float Rt[9];
#pragma unroll
    for (int i = 0; i < 3; i++)
#pragma unroll
        for (int j = 0; j < 3; j++)
            Rt[i*3 + j] = E[j*4 + i];
    float t0 = E[3], t1 = E[7], t2 = E[11];
    float tp[3];
#pragma unroll
    for (int i = 0; i < 3; i++)
        tp[i] = -(Rt[i*3+0]*t0 + Rt[i*3+1]*t1 + Rt[i*3+2]*t2);

    float* o = g_cam + bn * 12;
#pragma unroll
    for (int i = 0; i < 3; i++) {
#pragma unroll
        for (int j = 0; j < 3; j++)
            o[i*3 + j] = K[i*3+0]*Rt[0*3+j] + K[i*3+1]*Rt[1*3+j] + K[i*3+2]*Rt[2*3+j];
        o[9 + i] = K[i*3+0]*tp[0] + K[i*3+1]*tp[1] + K[i*3+2]*tp[2];
    }
}

// ---------------------------------------------------------------------------
// Kernel 2: HMMA GEMM per (b,n): featC[hw][o] = sum_c featH[hw][c] * W[o][c]
// BM=64, BN=256, BK=32; cp.async double-buffered + smem-staged coalesced
// epilogue. (R15 configuration — best measured conv variant, 16.3us)
// ---------------------------------------------------------------------------
#define GBM 64
#define GBK 32
#define ASTR 40       // 32 + 8 pad halves
#define BSTR 264      // 256 + 8 pad halves
#define ESTR 264      // epilogue staging stride
#define SMEM_BYTES (2*GBM*ASTR*2 + 2*GBK*BSTR*2)   // 44032

__device__ __forceinline__ uint32_t smem_u32(const void* p)
{
    return (uint32_t)__cvta_generic_to_shared(p);
}

__device__ __forceinline__ void cp_async16(uint32_t saddr, const void* gaddr)
{
    asm volatile("cp.async.cg.shared.global [%0], [%1], 16;" :: "r"(saddr), "l"(gaddr));
}
__device__ __forceinline__ void cp_commit()  { asm volatile("cp.async.commit_group;"); }
__device__ __forceinline__ void cp_wait0()   { asm volatile("cp.async.wait_group 0;"); }

__device__ __forceinline__ void ldm_x4(uint32_t* r, uint32_t addr)
{
    asm volatile("ldmatrix.sync.aligned.m8n8.x4.shared.b16 {%0,%1,%2,%3}, [%4];"
                 : "=r"(r[0]), "=r"(r[1]), "=r"(r[2]), "=r"(r[3]) : "r"(addr));
}
__device__ __forceinline__ void ldm_x4t(uint32_t* r, uint32_t addr)
{
    asm volatile("ldmatrix.sync.aligned.m8n8.x4.trans.shared.b16 {%0,%1,%2,%3}, [%4];"
                 : "=r"(r[0]), "=r"(r[1]), "=r"(r[2]), "=r"(r[3]) : "r"(addr));
}
__device__ __forceinline__ void mma16816(float* d, const uint32_t* a, const uint32_t* b)
{
    asm volatile("mma.sync.aligned.m16n8k16.row.col.f32.f16.f16.f32 "
                 "{%0,%1,%2,%3}, {%4,%5,%6,%7}, {%8,%9}, {%0,%1,%2,%3};"
                 : "+f"(d[0]), "+f"(d[1]), "+f"(d[2]), "+f"(d[3])
                 : "r"(a[0]), "r"(a[1]), "r"(a[2]), "r"(a[3]), "r"(b[0]), "r"(b[1]));
}

__global__ __launch_bounds__(256, 2) void conv_hmma()
{
    const int bn = blockIdx.y;              // 0..11
    const int m0 = blockIdx.x * GBM;

    __shared__ __align__(16) char smem_raw[SMEM_BYTES];
    __half (*As)[GBM * ASTR] = (__half(*)[GBM * ASTR])smem_raw;
    __half (*Bs)[GBK * BSTR] = (__half(*)[GBK * BSTR])(smem_raw + 2 * GBM * ASTR * 2);

    const int tid  = threadIdx.x;
    const int lane = tid & 31;
    const int wid  = tid >> 5;
    const int wm   = wid >> 2;              // 0..1
    const int wn   = wid & 3;               // 0..3

    const __half* A = g_featH + (size_t)bn * HWP * CCH;

    float acc[2][8][4];
#pragma unroll
    for (int i = 0; i < 2; i++)
#pragma unroll
        for (int j = 0; j < 8; j++)
#pragma unroll
            for (int q = 0; q < 4; q++) acc[i][j][q] = 0.f;

    const int ar = tid >> 2;                // A row 0..63
    const int ah = (tid & 3) * 8;           // A half-offset within 32

    cp_async16(smem_u32(&As[0][ar * ASTR + ah]),
               &A[(size_t)(m0 + ar) * CCH + ah]);
#pragma unroll
    for (int s = 0; s < 4; s++) {
        int v = tid + 256 * s;              // 0..1023
        int row = v >> 5, c = (v & 31) * 8;
        cp_async16(smem_u32(&Bs[0][row * BSTR + c]),
                   &g_whT[(size_t)row * CCH + c]);
    }
    cp_commit();
    cp_wait0();
    __syncthreads();

    int buf = 0;
#pragma unroll 1
    for (int kt = 0; kt < CCH / GBK; kt++) {
        const bool more = (kt + 1 < CCH / GBK);
        if (more) {
            int k0 = (kt + 1) * GBK;
            cp_async16(smem_u32(&As[buf ^ 1][ar * ASTR + ah]),
                       &A[(size_t)(m0 + ar) * CCH + k0 + ah]);
#pragma unroll
            for (int s = 0; s < 4; s++) {
                int v = tid + 256 * s;
                int row = v >> 5, c = (v & 31) * 8;
                cp_async16(smem_u32(&Bs[buf ^ 1][row * BSTR + c]),
                           &g_whT[(size_t)(k0 + row) * CCH + c]);
            }
            cp_commit();
        }

#pragma unroll
        for (int h = 0; h < 2; h++) {
            const int kk = h * 16;
            uint32_t af[2][4];
#pragma unroll
            for (int i = 0; i < 2; i++) {
                uint32_t addr = smem_u32(&As[buf][(wm*32 + i*16 + (lane & 15)) * ASTR
                                                  + (lane >> 4) * 8 + kk]);
                ldm_x4(af[i], addr);
            }
            uint32_t bf[8][2];
#pragma unroll
            for (int j4 = 0; j4 < 4; j4++) {
                uint32_t r[4];
                uint32_t addr = smem_u32(&Bs[buf][(kk + ((lane >> 3) & 1) * 8 + (lane & 7)) * BSTR
                                                  + wn*64 + j4*16 + (lane >> 4) * 8]);
                ldm_x4t(r, addr);
                bf[2*j4][0]   = r[0]; bf[2*j4][1]   = r[1];
                bf[2*j4+1][0] = r[2]; bf[2*j4+1][1] = r[3];
            }
#pragma unroll
            for (int i = 0; i < 2; i++)
#pragma unroll
                for (int j = 0; j < 8; j++)
                    mma16816(acc[i][j], af[i], bf[j]);
        }

        if (more) cp_wait0();
        __syncthreads();
        buf ^= 1;
    }

    // ---- Epilogue: stage fp16 tile in smem, then coalesced row stores ----
    __half* stg = (__half*)smem_raw;        // 64 x ESTR halves = 33792 B
    const int gid = lane >> 2;              // 0..7
    const int tig = lane & 3;               // 0..3
#pragma unroll
    for (int i = 0; i < 2; i++) {
        int r0 = wm*32 + i*16 + gid;
#pragma unroll
        for (int j = 0; j < 8; j++) {
            int c0 = wn*64 + j*8 + tig*2;
            *(__half2*)&stg[r0 * ESTR + c0]       = __floats2half2_rn(acc[i][j][0], acc[i][j][1]);
            *(__half2*)&stg[(r0 + 8) * ESTR + c0] = __floats2half2_rn(acc[i][j][2], acc[i][j][3]);
        }
    }
    __syncthreads();

    __half* D = g_featC + (size_t)bn * HWF * CCH;
#pragma unroll
    for (int pass = 0; pass < 8; pass++) {
        int row  = pass * 8 + wid;          // 0..63, one row per warp per pass
        int grow = m0 + row;
        if (grow < HWF) {
            uint4 v = *(const uint4*)&stg[row * ESTR + lane * 8];
            *(uint4*)&D[(size_t)grow * CCH + lane * 8] = v;
        }
    }
}

// ---------------------------------------------------------------------------
// Kernel 3: projection + record compaction (unchanged from 118us config)
// ---------------------------------------------------------------------------
__global__ __launch_bounds__(256) void proj_kernel(const float* __restrict__ pts)
{
    int t = blockIdx.x * blockDim.x + threadIdx.x;
    if (t >= BB * PP) return;
    int p = t % PP;
    int b = t / PP;

    const int base = (b * PP + p) * NR;
    int s = 0;

#pragma unroll
    for (int z = 0; z < ZZ; z++) {
        const float* q = pts + ((size_t)z * PP + p) * 3;
        float px = q[0], py = q[1], pz = q[2];
        float cnt = 0.f;

        int    ibuf[NC];
        float4 wbuf[NC];

#pragma unroll
        for (int n = 0; n < NC; n++) {
            const float* Cm = g_cam + (b * NC + n) * 12;
            float Zc = Cm[6]*px + Cm[7]*py + Cm[8]*pz + Cm[11];
            float inv = 1.f / (Zc + 1e-6f);
            float un = (Cm[0]*px + Cm[1]*py + Cm[2]*pz + Cm[9])  * inv * CU2 - 1.f;
            float vn = (Cm[3]*px + Cm[4]*py + Cm[5]*pz + Cm[10]) * inv * CV2 - 1.f;
            bool valid = (Zc > 0.1f) && (un >= -1.f) && (un <= 1.f) && (vn >= -1.f) && (vn <= 1.f);

            int off = -1;
            float4 w = make_float4(0.f, 0.f, 0.f, 0.f);
            if (valid) {
                float x = (un + 1.f) * 0.5f * (float)(FWW - 1);
                float y = (vn + 1.f) * 0.5f * (float)(FHH - 1);
                float x0f = floorf(x), y0f = floorf(y);
                float wx1 = x - x0f, wy1 = y - y0f;
                float wx0 = 1.f - wx1, wy0 = 1.f - wy1;
                int x0 = (int)x0f, y0 = (int)y0f;
                w = make_float4(wx0 * wy0, wx1 * wy0, wx0 * wy1, wx1 * wy1);
                if (x0 >= FWW - 1) { w.y = 0.f; w.w = 0.f; }  // x1 OOB -> weight 0
                if (y0 >= FHH - 1) { w.z = 0.f; w.w = 0.f; }
                off = (b * NC + n) * HWF + y0 * FWW + x0;
                cnt += 1.f;
            }
            ibuf[n] = off;
            wbuf[n] = w;
        }

        float icc = (1.f / (cnt + 1e-6f)) * (1.f / 3.f);
#pragma unroll
        for (int n = 0; n < NC; n++) {
            if (ibuf[n] >= 0) {
                float4 w = wbuf[n];
                w.x *= icc; w.y *= icc; w.z *= icc; w.w *= icc;
                g_crec[base + s] = ibuf[n];
                g_cw[base + s]   = w;
                s++;
            }
        }
    }
    g_cnt[b * PP + p] = s;
}

// ---------------------------------------------------------------------------
// Kernel 4: fp16 sampling (EXACT R12 configuration — the measured optimum;
// all structural perturbations regressed). Software-pipelined corner loads,
// packed f32x2 accumulation, smem BN table, coalesced transposed output.
// ---------------------------------------------------------------------------
__device__ __forceinline__ unsigned long long pack2f(float w)
{
    unsigned long long r;
    uint32_t u = __float_as_uint(w);
    asm("mov.b64 %0, {%1, %1};" : "=l"(r) : "r"(u));
    return r;
}

// acc: 4 packed float2 accumulators; q: 8 halves; w2: packed (w,w)
__device__ __forceinline__ void accum8x2(unsigned long long* acc, const uint4& q,
                                         unsigned long long w2)
{
    const __half2* h = (const __half2*)&q;
#pragma unroll
    for (int j = 0; j < 4; j++) {
        float2 f = __half22float2(h[j]);
        unsigned long long fu;
        memcpy(&fu, &f, 8);
        asm("fma.rn.f32x2 %0, %1, %2, %0;" : "+l"(acc[j]) : "l"(fu), "l"(w2));
    }
}

__global__ __launch_bounds__(256, 3) void sample_kernel(const float* __restrict__ convb,
                                                        const float* __restrict__ gamma,
                                                        const float* __restrict__ beta,
                                                        const float* __restrict__ mean,
                                                        const float* __restrict__ var,
                                                        float* __restrict__ out)
{
    __shared__ float so[16 * 257];
    __shared__ float ssc[CCH], sbi[CCH];

    const int b   = blockIdx.y;
    const int p0  = blockIdx.x * 32;
    const int tid = threadIdx.x;
    const int cg  = tid & 31;     // channel group (8 channels)
    const int ps  = tid >> 5;     // warp id = pixel sub-lane 0..7
    const int o0  = cg * 8;

    // BN + conv bias epilogue constants -> smem (one channel per thread)
    {
        float s = gamma[tid] * rsqrtf(var[tid] + 1e-5f);
        ssc[tid] = s;
        sbi[tid] = (convb[tid] - mean[tid]) * s + beta[tid];
    }
    __syncthreads();

    const uint4* fc = (const uint4*)g_featC;
    const size_t ob = (size_t)b * CCH * PP + p0;

#pragma unroll 1
    for (int chunk = 0; chunk < 2; chunk++) {
#pragma unroll 1
        for (int i = 0; i < 2; i++) {
            const int lp = i * 8 + ps;            // local pixel 0..15
            const int p  = p0 + chunk * 16 + lp;

            const int pb   = b * PP + p;
            const int cnt  = g_cnt[pb];
            const int base = pb * NR;

            unsigned long long acc[4] = {0ull, 0ull, 0ull, 0ull};

            // Pipeline prologue: meta for records 0,1; corner data for record 0.
            float4 w0   = g_cw[base];
            int    off1 = g_crec[base + 1];
            float4 w1   = g_cw[base + 1];
            {
                const uint4* f = fc + (size_t)g_crec[base] * 32 + cg;
                uint4 q0 = f[0], q1 = f[32], q2 = f[FWW * 32], q3 = f[(FWW + 1) * 32];

#pragma unroll 1
                for (int s = 0; s < cnt; s++) {
                    // fetch meta 2 ahead
                    int    off2 = g_crec[base + s + 2];
                    float4 w2v  = g_cw[base + s + 2];
                    // issue corner loads for record s+1 (off1 already resident)
                    const uint4* fn = fc + (size_t)off1 * 32 + cg;
                    uint4 n0 = fn[0], n1 = fn[32], n2 = fn[FWW * 32], n3 = fn[(FWW + 1) * 32];
                    // accumulate record s (loads issued one iteration ago)
                    accum8x2(acc, q0, pack2f(w0.x));
                    accum8x2(acc, q1, pack2f(w0.y));
                    accum8x2(acc, q2, pack2f(w0.z));
                    accum8x2(acc, q3, pack2f(w0.w));
                    // shift pipeline
                    q0 = n0; q1 = n1; q2 = n2; q3 = n3;
                    w0 = w1; w1 = w2v; off1 = off2;
                }
            }

            float ao[8];
            memcpy(ao, acc, 32);
            int row = lp * 257 + o0;
#pragma unroll
            for (int j = 0; j < 8; j++)
                so[row + j] = fmaxf(fmaf(ao[j], ssc[o0 + j], sbi[o0 + j]), 0.f);
        }
        __syncthreads();

        // Transposed write-out: 16 consecutive threads write 16 consecutive
        // pixels of one o-row (64B coalesced stores).
        const int px = tid & 15;
        const int og = tid >> 4;          // 0..15
#pragma unroll
        for (int ot = 0; ot < 16; ot++) {
            int o = og + ot * 16;
            out[ob + (size_t)o * PP + chunk * 16 + px] = so[px * 257 + o];
        }
        __syncthreads();
    }
}

// ---------------------------------------------------------------------------
// Launch: fork-join two-stream schedule. Chain B (prep_cam -> proj) runs on a
// side stream, overlapped with chain A (prep_w, prep_feats -> conv_hmma);
// both join before sample_kernel. Stream/events are created once (before the
// harness's graph capture, on the first correctness call) and reused — no
// per-call resource churn, identical captured work every call.
// ---------------------------------------------------------------------------
extern "C" void kernel_launch(void* const* d_in, const int* in_sizes, int n_in,
                              void* d_out, int out_size)
{
    const float* feats = (const float*)d_in[0];
    const float* intr  = (const float*)d_in[1];
    const float* extr  = (const float*)d_in[2];
    const float* pts   = (const float*)d_in[3];
    const float* convw = (const float*)d_in[4];
    const float* convb = (const float*)d_in[5];
    const float* gamma = (const float*)d_in[6];
    const float* beta  = (const float*)d_in[7];
    const float* mean  = (const float*)d_in[8];
    const float* var   = (const float*)d_in[9];
    float* out = (float*)d_out;

    static cudaStream_t s2 = nullptr;
    static cudaEvent_t  evFork = nullptr, evJoin = nullptr;
    if (s2 == nullptr) {
        cudaStreamCreateWithFlags(&s2, cudaStreamNonBlocking);
        cudaEventCreateWithFlags(&evFork, cudaEventDisableTiming);
        cudaEventCreateWithFlags(&evJoin, cudaEventDisableTiming);
    }

    // fork: chain B on s2
    cudaEventRecord(evFork, 0);
    cudaStreamWaitEvent(s2, evFork, 0);
    prep_cam<<<1, 32, 0, s2>>>(intr, extr);
    proj_kernel<<<(BB * PP + 255) / 256, 256, 0, s2>>>(pts);
    cudaEventRecord(evJoin, s2);

    // chain A on the main stream
    prep_w<<<256, 256>>>(convw);
    prep_feats<<<dim3(HWP/32, CCH/32, BB*NC), dim3(32, 8)>>>(feats);
    conv_hmma<<<dim3(HWP/GBM, BB*NC), 256>>>();

    // join, then sample
    cudaStreamWaitEvent(0, evJoin, 0);
    sample_kernel<<<dim3(PP / 32, BB), 256>>>(convb, gamma, beta, mean, var, out);
}